// round 5
// baseline (speedup 1.0000x reference)
#include <cuda_runtime.h>
#include <cstdint>

#define NB 4
#define NS 512
#define ND 768
#define NL 64

#define BM 64
#define BN 64
#define BK 32
#define LT 4

// Scratch for the rank-1 epilogue terms (allowed: __device__ globals).
__device__ float g_rowadd[NB * NL * NS];  // head . Wh + bias
__device__ float g_coladd[NB * NL * NS];  // dep  . Wd

__device__ __forceinline__ uint32_t f2tf(float x) {
    uint32_t r;
    asm("cvt.rna.tf32.f32 %0, %1;" : "=r"(r) : "f"(x));
    return r;
}

__device__ __forceinline__ void mma_tf32(float* c, const uint32_t* a,
                                         uint32_t b0, uint32_t b1) {
    asm volatile(
        "mma.sync.aligned.m16n8k8.row.col.f32.tf32.tf32.f32 "
        "{%0,%1,%2,%3}, {%4,%5,%6,%7}, {%8,%9}, {%0,%1,%2,%3};"
        : "+f"(c[0]), "+f"(c[1]), "+f"(c[2]), "+f"(c[3])
        : "r"(a[0]), "r"(a[1]), "r"(a[2]), "r"(a[3]), "r"(b0), "r"(b1));
}

// ---------------------------------------------------------------------------
// Stage 1: rowadd[b,l,i] = head[b,i,:] . W[l,0:768] + bias[l]
//          coladd[b,l,o] = dep [b,o,:] . W[l,768:1536]
// grid = (NB * NS/32, 2), block = 256.  gridDim.y selects head/dep path.
// ---------------------------------------------------------------------------
__global__ void __launch_bounds__(256) stage1_kernel(
    const float* __restrict__ head, const float* __restrict__ dep,
    const float* __restrict__ W, const float* __restrict__ bias)
{
    __shared__ float Xs[32][36];  // 32 rows of X, BK=32 cols, padded
    __shared__ float Ws[64][33];  // 64 label rows, padded (stride 33 -> conflict-free)

    const int which = blockIdx.y;          // 0: head/rowadd, 1: dep/coladd
    const float* X = which ? dep : head;
    const int b  = blockIdx.x >> 4;        // NS/32 = 16 chunks per batch
    const int i0 = (blockIdx.x & 15) * 32;

    const int t  = threadIdx.x;
    const int l  = t & 63;                 // label handled by this thread
    const int rg = t >> 6;                 // row group 0..3
    const int fr = t >> 3;                 // fill row 0..31
    const int fc = (t & 7) * 4;            // fill col (float4)

    float acc[8];
#pragma unroll
    for (int j = 0; j < 8; j++) acc[j] = 0.f;

    for (int k0 = 0; k0 < ND; k0 += 32) {
        __syncthreads();
        float4 xv = *(const float4*)&X[((size_t)(b * NS + i0 + fr)) * ND + k0 + fc];
        *(float4*)&Xs[fr][fc] = xv;
        float4 w0 = *(const float4*)&W[(size_t)fr * (2 * ND) + which * ND + k0 + fc];
        float4 w1 = *(const float4*)&W[(size_t)(fr + 32) * (2 * ND) + which * ND + k0 + fc];
        Ws[fr][fc + 0] = w0.x; Ws[fr][fc + 1] = w0.y;
        Ws[fr][fc + 2] = w0.z; Ws[fr][fc + 3] = w0.w;
        Ws[fr + 32][fc + 0] = w1.x; Ws[fr + 32][fc + 1] = w1.y;
        Ws[fr + 32][fc + 2] = w1.z; Ws[fr + 32][fc + 3] = w1.w;
        __syncthreads();
#pragma unroll
        for (int kk = 0; kk < 32; kk++) {
            float wv = Ws[l][kk];
#pragma unroll
            for (int j = 0; j < 8; j++)
                acc[j] += Xs[rg + 4 * j][kk] * wv;
        }
    }

    const float bb = which ? 0.f : bias[l];
    float* dst = which ? g_coladd : g_rowadd;
#pragma unroll
    for (int j = 0; j < 8; j++)
        dst[((size_t)(b * NL + l)) * NS + i0 + rg + 4 * j] = acc[j] + bb;
}

// ---------------------------------------------------------------------------
// Main kernel: per CTA, one 64x64 output tile for LT=4 labels of one batch.
// t1 via tf32 mma.sync; the U[l] diagonal is applied to the B fragment
// (2 FMULs per reg) so the head/dep smem tiles are shared across labels.
// grid = (NS/BN, NS/BM, NB * NL/LT) = (8, 8, 64), block = 256 (8 warps).
// Warp grid 2(m) x 4(n); warp tile 32x16; per-warp mma grid 2x2 per label.
// ---------------------------------------------------------------------------
__global__ void __launch_bounds__(256, 2) biaffine_main_kernel(
    const float* __restrict__ head, const float* __restrict__ dep,
    const float* __restrict__ U, float* __restrict__ out)
{
    __shared__ float As[BM][BK + 4];   // padded stride 36: conflict-free frag loads
    __shared__ float Bs[BN][BK + 4];
    __shared__ float Us[LT][BK];

    const int o0 = blockIdx.x * BN;
    const int i0 = blockIdx.y * BM;
    const int b  = blockIdx.z >> 4;          // NL/LT = 16 label groups
    const int l0 = (blockIdx.z & 15) * LT;

    const int t    = threadIdx.x;
    const int warp = t >> 5;
    const int lane = t & 31;
    const int wm   = warp >> 2;   // 0..1
    const int wn   = warp & 3;    // 0..3
    const int gid  = lane >> 2;   // 0..7
    const int tig  = lane & 3;    // 0..3

    float acc[LT][2][2][4];
#pragma unroll
    for (int l = 0; l < LT; l++)
#pragma unroll
        for (int mt = 0; mt < 2; mt++)
#pragma unroll
            for (int nt = 0; nt < 2; nt++)
#pragma unroll
                for (int q = 0; q < 4; q++) acc[l][mt][nt][q] = 0.f;

    // global fill pointers (each thread: 2 float4 for A, 2 for B, 1 U scalar)
    const int fr = t >> 3;        // 0..31
    const int fc = (t & 7) * 4;
    const float* hp = &head[((size_t)(b * NS + i0 + fr)) * ND + fc];
    const float* dp = &dep [((size_t)(b * NS + o0 + fr)) * ND + fc];
    const float* up = &U[(size_t)(l0 + ((t >> 5) & 3)) * ND + (t & 31)];

    float4 ha = *(const float4*)(hp);
    float4 hb = *(const float4*)(hp + 32 * ND);
    float4 da = *(const float4*)(dp);
    float4 db = *(const float4*)(dp + 32 * ND);
    float uv = (t < 128) ? up[0] : 0.f;

    for (int k0 = 0; k0 < ND; k0 += BK) {
        __syncthreads();
        {
            float4 v;
            v.x = __uint_as_float(f2tf(ha.x)); v.y = __uint_as_float(f2tf(ha.y));
            v.z = __uint_as_float(f2tf(ha.z)); v.w = __uint_as_float(f2tf(ha.w));
            *(float4*)&As[fr][fc] = v;
            v.x = __uint_as_float(f2tf(hb.x)); v.y = __uint_as_float(f2tf(hb.y));
            v.z = __uint_as_float(f2tf(hb.z)); v.w = __uint_as_float(f2tf(hb.w));
            *(float4*)&As[fr + 32][fc] = v;
            v.x = __uint_as_float(f2tf(da.x)); v.y = __uint_as_float(f2tf(da.y));
            v.z = __uint_as_float(f2tf(da.z)); v.w = __uint_as_float(f2tf(da.w));
            *(float4*)&Bs[fr][fc] = v;
            v.x = __uint_as_float(f2tf(db.x)); v.y = __uint_as_float(f2tf(db.y));
            v.z = __uint_as_float(f2tf(db.z)); v.w = __uint_as_float(f2tf(db.w));
            *(float4*)&Bs[fr + 32][fc] = v;
            if (t < 128) Us[t >> 5][t & 31] = uv;
        }
        __syncthreads();

        // software prefetch of next k-slice (overlaps with mma compute below)
        if (k0 + BK < ND) {
            ha = *(const float4*)(hp + k0 + BK);
            hb = *(const float4*)(hp + k0 + BK + 32 * ND);
            da = *(const float4*)(dp + k0 + BK);
            db = *(const float4*)(dp + k0 + BK + 32 * ND);
            if (t < 128) uv = up[k0 + BK];
        }

#pragma unroll
        for (int kt = 0; kt < 4; kt++) {
            const int kc = kt * 8 + tig;
            uint32_t a[2][4];
#pragma unroll
            for (int mt = 0; mt < 2; mt++) {
                const int rb = wm * 32 + mt * 16 + gid;
                a[mt][0] = __float_as_uint(As[rb    ][kc    ]);
                a[mt][1] = __float_as_uint(As[rb + 8][kc    ]);
                a[mt][2] = __float_as_uint(As[rb    ][kc + 4]);
                a[mt][3] = __float_as_uint(As[rb + 8][kc + 4]);
            }
            float bf[2][2];
#pragma unroll
            for (int nt = 0; nt < 2; nt++) {
                const int cb = wn * 16 + nt * 8 + gid;
                bf[nt][0] = Bs[cb][kc];
                bf[nt][1] = Bs[cb][kc + 4];
            }
#pragma unroll
            for (int l = 0; l < LT; l++) {
                const float u0 = Us[l][kt * 8 + tig];
                const float u1 = Us[l][kt * 8 + tig + 4];
#pragma unroll
                for (int nt = 0; nt < 2; nt++) {
                    // scale B fragment by the U diagonal (HW truncates to tf32)
                    const uint32_t b0 = __float_as_uint(bf[nt][0] * u0);
                    const uint32_t b1 = __float_as_uint(bf[nt][1] * u1);
                    mma_tf32(acc[l][0][nt], a[0], b0, b1);
                    mma_tf32(acc[l][1][nt], a[1], b0, b1);
                }
            }
        }
    }

    // epilogue: + rowadd[b,l,i] + coladd[b,l,o]  (bias already folded into rowadd)
#pragma unroll
    for (int l = 0; l < LT; l++) {
        const int lg = l0 + l;
        const float* radd = &g_rowadd[((size_t)(b * NL + lg)) * NS + i0];
        const float* cadd = &g_coladd[((size_t)(b * NL + lg)) * NS + o0];
        float* op = out + (((size_t)(b * NL + lg)) * NS + i0) * NS + o0;
#pragma unroll
        for (int mt = 0; mt < 2; mt++) {
            const int r0 = wm * 32 + mt * 16 + gid;
            const float ra0 = radd[r0];
            const float ra1 = radd[r0 + 8];
#pragma unroll
            for (int nt = 0; nt < 2; nt++) {
                const int c = wn * 16 + nt * 8 + 2 * tig;
                const float2 ca = *(const float2*)&cadd[c];
                float2 v0, v1;
                v0.x = acc[l][mt][nt][0] + ra0 + ca.x;
                v0.y = acc[l][mt][nt][1] + ra0 + ca.y;
                v1.x = acc[l][mt][nt][2] + ra1 + ca.x;
                v1.y = acc[l][mt][nt][3] + ra1 + ca.y;
                *(float2*)&op[(size_t)r0 * NS + c]       = v0;
                *(float2*)&op[(size_t)(r0 + 8) * NS + c] = v1;
            }
        }
    }
}

extern "C" void kernel_launch(void* const* d_in, const int* in_sizes, int n_in,
                              void* d_out, int out_size) {
    const float* head = (const float*)d_in[0];
    const float* dep  = (const float*)d_in[1];
    const float* U    = (const float*)d_in[2];
    const float* W    = (const float*)d_in[3];
    const float* bias = (const float*)d_in[4];
    float* out = (float*)d_out;

    stage1_kernel<<<dim3(NB * (NS / 32), 2), 256>>>(head, dep, W, bias);
    biaffine_main_kernel<<<dim3(NS / BN, NS / BM, NB * (NL / LT)), 256>>>(
        head, dep, U, out);
}

// round 7
// speedup vs baseline: 1.0619x; 1.0619x over previous
#include <cuda_runtime.h>
#include <cstdint>

#define NB 4
#define NS 512
#define ND 768
#define NL 64

#define BM 64
#define BN 64
#define BK 32
#define LT 4
#define NCH (ND / BK)   // 24

// SMEM (floats): As[2][64][36], Bs[2][64][36], Us[4][768]  -> 49152 bytes total
#define ST_STRIDE 36
#define ST_FLOATS (BM * ST_STRIDE)         // 2304 per stage per matrix
#define OFF_B (2 * ST_FLOATS)              // after As[2]
#define OFF_U (4 * ST_FLOATS)              // after Bs[2]
#define SMEM_BYTES ((4 * ST_FLOATS + LT * ND) * 4)

// Scratch for the rank-1 epilogue terms.
__device__ float g_rowadd[NB * NL * NS];  // head . Wh + bias
__device__ float g_coladd[NB * NL * NS];  // dep  . Wd

__device__ __forceinline__ uint32_t f2tf(float x) {
    uint32_t r;
    asm("cvt.rna.tf32.f32 %0, %1;" : "=r"(r) : "f"(x));
    return r;
}

__device__ __forceinline__ void mma_tf32(float* c, const uint32_t* a,
                                         uint32_t b0, uint32_t b1) {
    asm volatile(
        "mma.sync.aligned.m16n8k8.row.col.f32.tf32.tf32.f32 "
        "{%0,%1,%2,%3}, {%4,%5,%6,%7}, {%8,%9}, {%0,%1,%2,%3};"
        : "+f"(c[0]), "+f"(c[1]), "+f"(c[2]), "+f"(c[3])
        : "r"(a[0]), "r"(a[1]), "r"(a[2]), "r"(a[3]), "r"(b0), "r"(b1));
}

// ---------------------------------------------------------------------------
// Stage 1 (unchanged, known-good): rank-1 epilogue terms.
// ---------------------------------------------------------------------------
__global__ void __launch_bounds__(256) stage1_kernel(
    const float* __restrict__ head, const float* __restrict__ dep,
    const float* __restrict__ W, const float* __restrict__ bias)
{
    __shared__ float Xs[32][36];
    __shared__ float Ws[64][33];

    const int which = blockIdx.y;
    const float* X = which ? dep : head;
    const int b  = blockIdx.x >> 4;
    const int i0 = (blockIdx.x & 15) * 32;

    const int t  = threadIdx.x;
    const int l  = t & 63;
    const int rg = t >> 6;
    const int fr = t >> 3;
    const int fc = (t & 7) * 4;

    float acc[8];
#pragma unroll
    for (int j = 0; j < 8; j++) acc[j] = 0.f;

    for (int k0 = 0; k0 < ND; k0 += 32) {
        __syncthreads();
        float4 xv = *(const float4*)&X[((size_t)(b * NS + i0 + fr)) * ND + k0 + fc];
        *(float4*)&Xs[fr][fc] = xv;
        float4 w0 = *(const float4*)&W[(size_t)fr * (2 * ND) + which * ND + k0 + fc];
        float4 w1 = *(const float4*)&W[(size_t)(fr + 32) * (2 * ND) + which * ND + k0 + fc];
        Ws[fr][fc + 0] = w0.x; Ws[fr][fc + 1] = w0.y;
        Ws[fr][fc + 2] = w0.z; Ws[fr][fc + 3] = w0.w;
        Ws[fr + 32][fc + 0] = w1.x; Ws[fr + 32][fc + 1] = w1.y;
        Ws[fr + 32][fc + 2] = w1.z; Ws[fr + 32][fc + 3] = w1.w;
        __syncthreads();
#pragma unroll
        for (int kk = 0; kk < 32; kk++) {
            float wv = Ws[l][kk];
#pragma unroll
            for (int j = 0; j < 8; j++)
                acc[j] += Xs[rg + 4 * j][kk] * wv;
        }
    }

    const float bb = which ? 0.f : bias[l];
    float* dst = which ? g_coladd : g_rowadd;
#pragma unroll
    for (int j = 0; j < 8; j++)
        dst[((size_t)(b * NL + l)) * NS + i0 + rg + 4 * j] = acc[j] + bb;
}

// ---------------------------------------------------------------------------
// Main kernel: tf32 mma.sync, 2-stage double buffer, ONE barrier per chunk.
// Per iteration: LDG next chunk -> MMAs on current stage -> cvt+STS to other
// stage -> __syncthreads. U rows for the CTA's 4 labels are SMEM-resident.
// grid = (8, 8, 64), block = 256 (8 warps, 2x4 warp grid, 32x16 warp tile).
// ---------------------------------------------------------------------------
__global__ void __launch_bounds__(256, 2) biaffine_main_kernel(
    const float* __restrict__ head, const float* __restrict__ dep,
    const float* __restrict__ U, float* __restrict__ out)
{
    extern __shared__ float smf[];
    float* AsBase = smf;            // [2][64][36]
    float* BsBase = smf + OFF_B;    // [2][64][36]
    float* Us     = smf + OFF_U;    // [4][768]

    const int o0 = blockIdx.x * BN;
    const int i0 = blockIdx.y * BM;
    const int b  = blockIdx.z >> 4;
    const int l0 = (blockIdx.z & 15) * LT;

    const int t    = threadIdx.x;
    const int warp = t >> 5;
    const int lane = t & 31;
    const int wm   = warp >> 2;   // 0..1
    const int wn   = warp & 3;    // 0..3
    const int gid  = lane >> 2;   // 0..7
    const int tig  = lane & 3;    // 0..3

    float acc[LT][2][2][4];
#pragma unroll
    for (int l = 0; l < LT; l++)
#pragma unroll
        for (int mt = 0; mt < 2; mt++)
#pragma unroll
            for (int nt = 0; nt < 2; nt++)
#pragma unroll
                for (int q = 0; q < 4; q++) acc[l][mt][nt][q] = 0.f;

    // Preload the 4 U rows (contiguous 3072 floats) into SMEM once.
    {
        const float4* usrc = (const float4*)(U + (size_t)l0 * ND);
        float4* udst = (float4*)Us;
#pragma unroll
        for (int j = 0; j < 3; j++)
            udst[t + 256 * j] = __ldg(&usrc[t + 256 * j]);
    }

    const int fr = t >> 3;        // 0..31
    const int fc = (t & 7) * 4;
    const float* hp = &head[((size_t)(b * NS + i0 + fr)) * ND + fc];
    const float* dp = &dep [((size_t)(b * NS + o0 + fr)) * ND + fc];

    // Fill stage 0 with chunk 0.
    {
        float4 ha = *(const float4*)(hp);
        float4 hb = *(const float4*)(hp + 32 * ND);
        float4 da = *(const float4*)(dp);
        float4 db = *(const float4*)(dp + 32 * ND);
        float4 v;
        v.x = __uint_as_float(f2tf(ha.x)); v.y = __uint_as_float(f2tf(ha.y));
        v.z = __uint_as_float(f2tf(ha.z)); v.w = __uint_as_float(f2tf(ha.w));
        *(float4*)&AsBase[fr * ST_STRIDE + fc] = v;
        v.x = __uint_as_float(f2tf(hb.x)); v.y = __uint_as_float(f2tf(hb.y));
        v.z = __uint_as_float(f2tf(hb.z)); v.w = __uint_as_float(f2tf(hb.w));
        *(float4*)&AsBase[(fr + 32) * ST_STRIDE + fc] = v;
        v.x = __uint_as_float(f2tf(da.x)); v.y = __uint_as_float(f2tf(da.y));
        v.z = __uint_as_float(f2tf(da.z)); v.w = __uint_as_float(f2tf(da.w));
        *(float4*)&BsBase[fr * ST_STRIDE + fc] = v;
        v.x = __uint_as_float(f2tf(db.x)); v.y = __uint_as_float(f2tf(db.y));
        v.z = __uint_as_float(f2tf(db.z)); v.w = __uint_as_float(f2tf(db.w));
        *(float4*)&BsBase[(fr + 32) * ST_STRIDE + fc] = v;
    }
    __syncthreads();

    for (int ch = 0; ch < NCH; ch++) {
        const int cur = ch & 1;
        const int k0 = ch * BK;
        const bool more = (ch < NCH - 1);

        // 1) LDG next chunk into registers (latency hidden by MMAs below).
        float4 ha, hb, da, db;
        if (more) {
            ha = *(const float4*)(hp + k0 + BK);
            hb = *(const float4*)(hp + k0 + BK + 32 * ND);
            da = *(const float4*)(dp + k0 + BK);
            db = *(const float4*)(dp + k0 + BK + 32 * ND);
        }

        // 2) MMAs on current stage.
        const float* Ac = AsBase + cur * ST_FLOATS;
        const float* Bc = BsBase + cur * ST_FLOATS;
        const float* ub = Us + k0;
#pragma unroll
        for (int kt = 0; kt < 4; kt++) {
            const int kc = kt * 8 + tig;
            uint32_t a[2][4];
#pragma unroll
            for (int mt = 0; mt < 2; mt++) {
                const int rb = wm * 32 + mt * 16 + gid;
                a[mt][0] = __float_as_uint(Ac[rb * ST_STRIDE + kc]);
                a[mt][1] = __float_as_uint(Ac[(rb + 8) * ST_STRIDE + kc]);
                a[mt][2] = __float_as_uint(Ac[rb * ST_STRIDE + kc + 4]);
                a[mt][3] = __float_as_uint(Ac[(rb + 8) * ST_STRIDE + kc + 4]);
            }
            float bf[2][2];
#pragma unroll
            for (int nt = 0; nt < 2; nt++) {
                const int cb = wn * 16 + nt * 8 + gid;
                bf[nt][0] = Bc[cb * ST_STRIDE + kc];
                bf[nt][1] = Bc[cb * ST_STRIDE + kc + 4];
            }
#pragma unroll
            for (int l = 0; l < LT; l++) {
                const float u0 = ub[l * ND + kt * 8 + tig];
                const float u1 = ub[l * ND + kt * 8 + tig + 4];
#pragma unroll
                for (int nt = 0; nt < 2; nt++) {
                    const uint32_t b0 = __float_as_uint(bf[nt][0] * u0);
                    const uint32_t b1 = __float_as_uint(bf[nt][1] * u1);
                    mma_tf32(acc[l][0][nt], a[0], b0, b1);
                    mma_tf32(acc[l][1][nt], a[1], b0, b1);
                }
            }
        }

        // 3) cvt + STS into the other stage.
        if (more) {
            float* An = AsBase + (cur ^ 1) * ST_FLOATS;
            float* Bn = BsBase + (cur ^ 1) * ST_FLOATS;
            float4 v;
            v.x = __uint_as_float(f2tf(ha.x)); v.y = __uint_as_float(f2tf(ha.y));
            v.z = __uint_as_float(f2tf(ha.z)); v.w = __uint_as_float(f2tf(ha.w));
            *(float4*)&An[fr * ST_STRIDE + fc] = v;
            v.x = __uint_as_float(f2tf(hb.x)); v.y = __uint_as_float(f2tf(hb.y));
            v.z = __uint_as_float(f2tf(hb.z)); v.w = __uint_as_float(f2tf(hb.w));
            *(float4*)&An[(fr + 32) * ST_STRIDE + fc] = v;
            v.x = __uint_as_float(f2tf(da.x)); v.y = __uint_as_float(f2tf(da.y));
            v.z = __uint_as_float(f2tf(da.z)); v.w = __uint_as_float(f2tf(da.w));
            *(float4*)&Bn[fr * ST_STRIDE + fc] = v;
            v.x = __uint_as_float(f2tf(db.x)); v.y = __uint_as_float(f2tf(db.y));
            v.z = __uint_as_float(f2tf(db.z)); v.w = __uint_as_float(f2tf(db.w));
            *(float4*)&Bn[(fr + 32) * ST_STRIDE + fc] = v;
            __syncthreads();   // one barrier per chunk
        }
    }

    // Epilogue: + rowadd[b,l,i] + coladd[b,l,o]  (bias folded into rowadd).
#pragma unroll
    for (int l = 0; l < LT; l++) {
        const int lg = l0 + l;
        const float* radd = &g_rowadd[((size_t)(b * NL + lg)) * NS + i0];
        const float* cadd = &g_coladd[((size_t)(b * NL + lg)) * NS + o0];
        float* op = out + (((size_t)(b * NL + lg)) * NS + i0) * NS + o0;
#pragma unroll
        for (int mt = 0; mt < 2; mt++) {
            const int r0 = wm * 32 + mt * 16 + gid;
            const float ra0 = radd[r0];
            const float ra1 = radd[r0 + 8];
#pragma unroll
            for (int nt = 0; nt < 2; nt++) {
                const int c = wn * 16 + nt * 8 + 2 * tig;
                const float2 ca = *(const float2*)&cadd[c];
                float2 v0, v1;
                v0.x = acc[l][mt][nt][0] + ra0 + ca.x;
                v0.y = acc[l][mt][nt][1] + ra0 + ca.y;
                v1.x = acc[l][mt][nt][2] + ra1 + ca.x;
                v1.y = acc[l][mt][nt][3] + ra1 + ca.y;
                *(float2*)&op[(size_t)r0 * NS + c]       = v0;
                *(float2*)&op[(size_t)(r0 + 8) * NS + c] = v1;
            }
        }
    }
}

extern "C" void kernel_launch(void* const* d_in, const int* in_sizes, int n_in,
                              void* d_out, int out_size) {
    const float* head = (const float*)d_in[0];
    const float* dep  = (const float*)d_in[1];
    const float* U    = (const float*)d_in[2];
    const float* W    = (const float*)d_in[3];
    const float* bias = (const float*)d_in[4];
    float* out = (float*)d_out;

    cudaFuncSetAttribute(biaffine_main_kernel,
                         cudaFuncAttributeMaxDynamicSharedMemorySize, SMEM_BYTES);

    stage1_kernel<<<dim3(NB * (NS / 32), 2), 256>>>(head, dep, W, bias);
    biaffine_main_kernel<<<dim3(NS / BN, NS / BM, NB * (NL / LT)), 256, SMEM_BYTES>>>(
        head, dep, U, out);
}